// round 14
// baseline (speedup 1.0000x reference)
#include <cuda_runtime.h>
#include <cuda_fp16.h>
#include <cstdint>

// ---------------- problem constants ----------------
#define C_CH   256
#define H_F    50
#define W_F    50
#define N_IMG  2
#define NROI   1000
#define MPAD   1024
#define KB     12544          // 256*49
#define HID    1024
#define NCLS   81

// ---------------- scratch (device globals; no allocs) ----------------
__device__ __half  g_feath[N_IMG * H_F * W_F * C_CH];  // NHWC fp16
__device__ __half  g_xh  [MPAD * KB];                  // pooled x, fp16, [k][p*256+c]
__device__ __half  g_W1h [HID * KB];                   // fp16 [n][k], k-order = p*256+c
__device__ __half  g_Wc1h[HID * KB];
__device__ __half  g_W2h [HID * HID];                  // fp16 [n][k]
__device__ __half  g_h1h [MPAD * HID];                 // h1 fp16
__device__ float   g_part[4 * MPAD * HID];             // split-K fp32 partials (16 MB)
__device__ float   g_c  [NROI * HID];
__device__ float   g_h2 [NROI * HID];
__device__ float   g_W3t [4 * HID];
__device__ float   g_Wc2t[NCLS * HID];

// ---------------- streams/events (created pre-main, before harness checkpoints) ----------------
struct SideStream {
    cudaStream_t s2 = nullptr;
    cudaEvent_t  evFork = nullptr, evJoin = nullptr;
    SideStream() {
        cudaFree(0);   // establish context
        cudaStreamCreateWithFlags(&s2, cudaStreamNonBlocking);
        cudaEventCreateWithFlags(&evFork, cudaEventDisableTiming);
        cudaEventCreateWithFlags(&evJoin, cudaEventDisableTiming);
    }
};
static SideStream g_ss;

// ---------------- small PTX helpers ----------------
__device__ __forceinline__ uint32_t smem_u32(const void* p) {
    uint32_t a;
    asm("{ .reg .u64 t; cvta.to.shared.u64 t, %1; cvt.u32.u64 %0, t; }" : "=r"(a) : "l"(p));
    return a;
}
__device__ __forceinline__ void cp16(uint32_t d, const void* s) {
    asm volatile("cp.async.cg.shared.global [%0], [%1], 16;" :: "r"(d), "l"(s));
}
#define CP_COMMIT() asm volatile("cp.async.commit_group;" ::: "memory")
#define CP_WAIT3()  asm volatile("cp.async.wait_group 3;"  ::: "memory")

#define LDSM4(f, addr) \
    asm volatile("ldmatrix.sync.aligned.m8n8.x4.shared.b16 {%0,%1,%2,%3}, [%4];" \
        : "=r"((f)[0]), "=r"((f)[1]), "=r"((f)[2]), "=r"((f)[3]) : "r"(addr))

#define MMA16816(d, a, bl, bh) \
    asm volatile("mma.sync.aligned.m16n8k16.row.col.f32.f16.f16.f32 " \
        "{%0,%1,%2,%3},{%4,%5,%6,%7},{%8,%9},{%0,%1,%2,%3};" \
        : "+f"((d)[0]), "+f"((d)[1]), "+f"((d)[2]), "+f"((d)[3]) \
        : "r"((a)[0]), "r"((a)[1]), "r"((a)[2]), "r"((a)[3]), "r"(bl), "r"(bh))

// ---------------- 1) NCHW fp32 -> NHWC fp16 ----------------
__global__ void nchw2nhwc(const float* __restrict__ f) {
    int idx = blockIdx.x * 256 + threadIdx.x;
    const int total = N_IMG * H_F * W_F * C_CH;
    if (idx >= total) return;
    int c = idx & 255;
    int rest = idx >> 8;
    int w = rest % W_F; rest /= W_F;
    int h = rest % H_F;
    int n = rest / H_F;
    g_feath[idx] = __float2half_rn(f[((n * C_CH + c) * H_F + h) * W_F + w]);
}

// ---------------- 2) RoIAlign (fp16 gather) -> fp16 x ----------------
__global__ void roi_align_kernel(const float* __restrict__ props) {
    int k = blockIdx.x;
    int c = threadIdx.x;          // 0..127, channels 2c, 2c+1

    __shared__ int   s_i0y[14], s_i1y[14], s_i0x[14], s_i1x[14];
    __shared__ float s_wly[14], s_why[14], s_wlx[14], s_whx[14];
    __shared__ int   s_vy[14], s_vx[14];
    __shared__ int   s_b;

    if (c == 0) s_b = (int)props[k * 5];
    if (c < 28) {
        int axis = c / 14;
        int q    = c % 14;
        float lo = props[k * 5 + (axis ? 1 : 2)] * (1.0f / 16.0f);
        float hi = props[k * 5 + (axis ? 3 : 4)] * (1.0f / 16.0f);
        float ext = fmaxf(hi - lo, 1.0f);
        float bin = ext / 7.0f;
        int p = q >> 1, s = q & 1;
        float t = (float)p + ((float)s + 0.5f) * 0.5f;
        float y = lo + t * bin;
        int valid = (y > -1.0f) && (y < 50.0f);
        float yc = fminf(fmaxf(y, 0.0f), 49.0f);
        int i0 = (int)floorf(yc);
        int i1 = min(i0 + 1, 49);
        float whi = yc - (float)i0;
        float wlo = 1.0f - whi;
        if (axis == 0) { s_vy[q]=valid; s_i0y[q]=i0; s_i1y[q]=i1; s_wly[q]=wlo; s_why[q]=whi; }
        else           { s_vx[q]=valid; s_i0x[q]=i0; s_i1x[q]=i1; s_wlx[q]=wlo; s_whx[q]=whi; }
    }
    __syncthreads();

    const __half* F = g_feath + (size_t)s_b * (H_F * W_F * C_CH) + 2 * c;
    size_t ob = (size_t)k * KB + 2 * c;

    #pragma unroll 1
    for (int p = 0; p < 49; p++) {
        int by = p / 7, bx = p % 7;
        float ax = 0.0f, ay = 0.0f;
        #pragma unroll
        for (int sy = 0; sy < 2; sy++) {
            int qy = by * 2 + sy;
            if (!s_vy[qy]) continue;
            const __half* Fy0 = F + s_i0y[qy] * (W_F * C_CH);
            const __half* Fy1 = F + s_i1y[qy] * (W_F * C_CH);
            float wly = s_wly[qy], why = s_why[qy];
            #pragma unroll
            for (int sx = 0; sx < 2; sx++) {
                int qx = bx * 2 + sx;
                if (!s_vx[qx]) continue;
                int o0 = s_i0x[qx] * C_CH, o1 = s_i1x[qx] * C_CH;
                float2 f00 = __half22float2(*(const __half2*)(Fy0 + o0));
                float2 f01 = __half22float2(*(const __half2*)(Fy0 + o1));
                float2 f10 = __half22float2(*(const __half2*)(Fy1 + o0));
                float2 f11 = __half22float2(*(const __half2*)(Fy1 + o1));
                float wlx = s_wlx[qx], whx = s_whx[qx];
                ax += wly * (wlx * f00.x + whx * f01.x) + why * (wlx * f10.x + whx * f11.x);
                ay += wly * (wlx * f00.y + whx * f01.y) + why * (wlx * f10.y + whx * f11.y);
            }
        }
        *(__half2*)&g_xh[ob + (size_t)p * C_CH] = __floats2half2_rn(ax * 0.25f, ay * 0.25f);
    }
}

// ---------------- 3a) W1+Wc1 prep (fused): W[c*49+p][n] -> fp16 [n][p*256+c] ----------------
__global__ __launch_bounds__(256) void prep_big(const float* __restrict__ WA,
                                                const float* __restrict__ WB) {
    __shared__ float s[64][65];
    int zz = blockIdx.z;
    int p  = zz >> 1;
    const float* W = (zz & 1) ? WB : WA;
    __half* O = (zz & 1) ? g_Wc1h : g_W1h;
    int c0 = blockIdx.y << 6;
    int n0 = blockIdx.x << 6;
    for (int i = threadIdx.x; i < 4096; i += 256) {
        int ci = i >> 6, ni = i & 63;
        s[ci][ni] = W[(size_t)((c0 + ci) * 49 + p) * HID + n0 + ni];
    }
    __syncthreads();
    for (int i = threadIdx.x; i < 2048; i += 256) {
        int ni = i >> 5, c2 = (i & 31) * 2;
        __half2 hv = __floats2half2_rn(s[c2][ni], s[c2 + 1][ni]);
        *(__half2*)&O[(size_t)(n0 + ni) * KB + p * 256 + c0 + c2] = hv;
    }
}

// ---------------- 3b) W2 prep: W2[k][n] -> fp16 [n][k] ----------------
__global__ __launch_bounds__(256) void prep_w2(const float* __restrict__ W) {
    __shared__ float s[64][65];
    int k0 = blockIdx.y << 6;
    int n0 = blockIdx.x << 6;
    for (int i = threadIdx.x; i < 4096; i += 256) {
        int ki = i >> 6, ni = i & 63;
        s[ki][ni] = W[(size_t)(k0 + ki) * HID + n0 + ni];
    }
    __syncthreads();
    for (int i = threadIdx.x; i < 2048; i += 256) {
        int ni = i >> 5, k2 = (i & 31) * 2;
        __half2 hv = __floats2half2_rn(s[k2][ni], s[k2 + 1][ni]);
        *(__half2*)&g_W2h[(size_t)(n0 + ni) * HID + k0 + k2] = hv;
    }
}

// ---------------- 3c) head-weight transposes ----------------
__global__ void prep_heads(const float* __restrict__ W3, const float* __restrict__ Wc2) {
    int i = blockIdx.x * 256 + threadIdx.x;
    if (i < 4 * HID) {
        g_W3t[(i & 3) * HID + (i >> 2)] = W3[i];
    }
    int j = i - 4 * HID;
    if (j >= 0 && j < NCLS * HID) {
        g_Wc2t[(j % NCLS) * HID + (j / NCLS)] = Wc2[j];
    }
}

// ---------------- 4) split-K fp16 HMMA GEMM (fp32 partials out) ----------------
// CTA 128(M)x128(N), BK=32, 512 threads (16 warps, 4x4 grid, warp tile 32x32),
// 5-stage cp.async (102.4KB smem) -> 2 CTAs/SM = 32 warps/SM.
#define BM 128
#define BN 128
#define BK 32
#define NSTAGE 5
#define ROWB 80                          // 64B data + 16B pad
#define A_TILE (128 * ROWB)              // 10240
#define B_OFF  A_TILE
#define STAGE_BYTES (256 * ROWB)         // 20480
#define SMEM_TOTAL (NSTAGE * STAGE_BYTES)    // 102400

__global__ void __launch_bounds__(512, 2) gemm_sk(
    const __half* __restrict__ A,
    const __half* __restrict__ Ba, const __half* __restrict__ Bb,
    float* __restrict__ part,
    int K, int nsplit, int chunks_per_split)
{
    extern __shared__ char sm[];
    const int tid  = threadIdx.x;
    const int lane = tid & 31;
    const int wid  = tid >> 5;
    const int warp_m = wid & 3;          // 0..3  (32-row slabs)
    const int warp_n = wid >> 2;         // 0..3  (32-col slabs)
    const int row0 = blockIdx.y * BM;
    const int col0 = blockIdx.x * BN;
    const int zpart = blockIdx.z / nsplit;
    const int ks    = blockIdx.z - zpart * nsplit;
    const int chunk0 = ks * chunks_per_split;

    const __half* B = zpart ? Bb : Ba;
    float* pout = part + (size_t)blockIdx.z * (MPAD * HID);

    const uint32_t sbase = smem_u32(sm);
    const int nch = chunks_per_split;

    // cp.async: threads 0..255 load A, 256..511 load B.
    const int halfsel = tid >> 8;                 // 0 = A, 1 = B
    const int lr = (tid & 255) >> 1;
    const int lc = (tid & 1) * 32;
    const __half* gsrcm = halfsel ? (B + (size_t)(col0 + lr) * K)
                                  : (A + (size_t)(row0 + lr) * K);
    const char* gsrc = (const char*)gsrcm + lc;
    const uint32_t sdst = sbase + halfsel * A_TILE + lr * ROWB + lc;

    #define ISSUE(st, kc) do {                                        \
        size_t go = (size_t)(chunk0 + (kc)) * (BK * 2);                \
        uint32_t dd = sdst + (st) * STAGE_BYTES;                       \
        const char* pp = gsrc + go;                                    \
        cp16(dd,      pp);                                             \
        cp16(dd + 16, pp + 16);                                        \
        CP_COMMIT();                                                   \
    } while (0)

    ISSUE(0, 0); ISSUE(1, 1); ISSUE(2, 2); ISSUE(3, 3);

    float acc[2][4][4] = {};
    const uint32_t lrow = (lane & 15) * ROWB + ((lane >> 4) * 16);

    for (int kc = 0; kc < nch; kc++) {
        CP_WAIT3();
        __syncthreads();

        if (kc + 4 < nch) {
            ISSUE((kc + 4) % NSTAGE, kc + 4);
        } else {
            CP_COMMIT();   // keep group accounting uniform for CP_WAIT3
        }

        const int st = kc % NSTAGE;
        const uint32_t sAh = sbase + st * STAGE_BYTES + (warp_m * 32) * ROWB + lrow;
        const uint32_t sBs = sbase + st * STAGE_BYTES + B_OFF + (warp_n * 32) * ROWB + lrow;

        #pragma unroll
        for (int ksi = 0; ksi < 2; ksi++) {
            uint32_t af[2][4], bf[2][4];
            LDSM4(af[0], sAh + ksi * 32);
            LDSM4(af[1], sAh + 16 * ROWB + ksi * 32);
            LDSM4(bf[0], sBs + ksi * 32);
            LDSM4(bf[1], sBs + 16 * ROWB + ksi * 32);
            #pragma unroll
            for (int mt = 0; mt < 2; mt++)
                #pragma unroll
                for (int nt = 0; nt < 4; nt++)
                    MMA16816(acc[mt][nt], af[mt],
                             bf[nt >> 1][nt & 1], bf[nt >> 1][(nt & 1) + 2]);
        }
    }

    // ---------------- epilogue: raw fp32 partials ----------------
    #pragma unroll
    for (int mt = 0; mt < 2; mt++) {
        #pragma unroll
        for (int half = 0; half < 2; half++) {
            int r = row0 + warp_m * 32 + mt * 16 + (lane >> 2) + half * 8;
            #pragma unroll
            for (int nt = 0; nt < 4; nt++) {
                int ccol = col0 + warp_n * 32 + nt * 8 + (lane & 3) * 2;
                float2 v = make_float2(acc[mt][nt][half * 2 + 0],
                                       acc[mt][nt][half * 2 + 1]);
                *(float2*)&pout[(size_t)r * HID + ccol] = v;
            }
        }
    }
    #undef ISSUE
}

// ---------------- 4b) finalize GEMM1: h1 = relu(p0+p1+b1) fp16; c = relu(p2+p3+bc1) f32 ----------------
__global__ __launch_bounds__(256) void finalize1(const float* __restrict__ b1,
                                                 const float* __restrict__ bc1) {
    int idx4 = blockIdx.x * 256 + threadIdx.x;      // 1M/4 = 262144 idx4
    int base = idx4 * 4;
    int m = base >> 10;
    int n = base & 1023;
    const float* p = g_part;
    float4 p0 = *(const float4*)&p[0 * MPAD * HID + base];
    float4 p1 = *(const float4*)&p[1 * MPAD * HID + base];
    float4 bb = *(const float4*)&b1[n];
    float4 h;
    h.x = fmaxf(p0.x + p1.x + bb.x, 0.0f);
    h.y = fmaxf(p0.y + p1.y + bb.y, 0.0f);
    h.z = fmaxf(p0.z + p1.z + bb.z, 0.0f);
    h.w = fmaxf(p0.w + p1.w + bb.w, 0.0f);
    __half2 o0 = __floats2half2_rn(h.x, h.y);
    __half2 o1 = __floats2half2_rn(h.z, h.w);
    *(__half2*)&g_h1h[base]     = o0;
    *(__half2*)&g_h1h[base + 2] = o1;

    if (m < NROI) {
        float4 p2 = *(const float4*)&p[2 * MPAD * HID + base];
        float4 p3 = *(const float4*)&p[3 * MPAD * HID + base];
        float4 bc = *(const float4*)&bc1[n];
        float4 cv;
        cv.x = fmaxf(p2.x + p3.x + bc.x, 0.0f);
        cv.y = fmaxf(p2.y + p3.y + bc.y, 0.0f);
        cv.z = fmaxf(p2.z + p3.z + bc.z, 0.0f);
        cv.w = fmaxf(p2.w + p3.w + bc.w, 0.0f);
        *(float4*)&g_c[base] = cv;
    }
}

// ---------------- 4c) finalize GEMM2: h2 = relu(p0+p1+p2+p3+b2) f32 (rows < NROI) ----------------
__global__ __launch_bounds__(256) void finalize2(const float* __restrict__ b2) {
    int idx4 = blockIdx.x * 256 + threadIdx.x;      // over NROI*HID/4
    int base = idx4 * 4;
    if (base >= NROI * HID) return;
    int n = base & 1023;
    const float* p = g_part;
    float4 p0 = *(const float4*)&p[0 * MPAD * HID + base];
    float4 p1 = *(const float4*)&p[1 * MPAD * HID + base];
    float4 p2 = *(const float4*)&p[2 * MPAD * HID + base];
    float4 p3 = *(const float4*)&p[3 * MPAD * HID + base];
    float4 bb = *(const float4*)&b2[n];
    float4 h;
    h.x = fmaxf(p0.x + p1.x + p2.x + p3.x + bb.x, 0.0f);
    h.y = fmaxf(p0.y + p1.y + p2.y + p3.y + bb.y, 0.0f);
    h.z = fmaxf(p0.z + p1.z + p2.z + p3.z + bb.z, 0.0f);
    h.w = fmaxf(p0.w + p1.w + p2.w + p3.w + bb.w, 0.0f);
    *(float4*)&g_h2[base] = h;
}

// ---------------- 5) heads: 8 rois per block, weight rows shared ----------------
#define HEADS_G 8
__global__ void heads_kernel(const float* __restrict__ b3, const float* __restrict__ bc2,
                             float* __restrict__ out)
{
    extern __shared__ float s[];          // [8*1024 h2 | 8*1024 c]
    float* sh = s;
    float* sc = s + HEADS_G * HID;
    int g0 = blockIdx.x * HEADS_G;
    int lane = threadIdx.x & 31;
    int wid  = threadIdx.x >> 5;          // 8 warps

    for (int i = threadIdx.x; i < HEADS_G * HID; i += blockDim.x) {
        int r = g0 + (i >> 10), kk = i & 1023;
        sh[i] = g_h2[(size_t)r * HID + kk];
        sc[i] = g_c [(size_t)r * HID + kk];
    }
    __syncthreads();

    for (int j = wid; j < 4 + NCLS; j += 8) {
        const float* wrow;
        const float* src;
        float bv;
        if (j < 4) { wrow = g_W3t  + (size_t)j * HID;       src = sh; bv = b3[j]; }
        else       { wrow = g_Wc2t + (size_t)(j - 4) * HID; src = sc; bv = bc2[j - 4]; }
        float a[HEADS_G] = {};
        for (int kk = lane; kk < HID; kk += 32) {
            float wv = wrow[kk];
            #pragma unroll
            for (int g = 0; g < HEADS_G; g++)
                a[g] += src[g * HID + kk] * wv;
        }
        #pragma unroll
        for (int g = 0; g < HEADS_G; g++) {
            #pragma unroll
            for (int o = 16; o > 0; o >>= 1) a[g] += __shfl_xor_sync(0xFFFFFFFFu, a[g], o);
        }
        if (lane == 0) {
            #pragma unroll
            for (int g = 0; g < HEADS_G; g++) {
                int k = g0 + g;
                if (j < 4) out[k * 4 + j] = a[g] + bv;
                else       out[NROI * 4 + k * NCLS + (j - 4)] = a[g] + bv;
            }
        }
    }
}

// ---------------- launch ----------------
extern "C" void kernel_launch(void* const* d_in, const int* in_sizes, int n_in,
                              void* d_out, int out_size)
{
    const float* features  = (const float*)d_in[0];
    const float* proposals = (const float*)d_in[1];
    const float* W1  = (const float*)d_in[2];
    const float* b1  = (const float*)d_in[3];
    const float* W2  = (const float*)d_in[4];
    const float* b2  = (const float*)d_in[5];
    const float* W3  = (const float*)d_in[6];
    const float* b3  = (const float*)d_in[7];
    const float* Wc1 = (const float*)d_in[8];
    const float* bc1 = (const float*)d_in[9];
    const float* Wc2 = (const float*)d_in[10];
    const float* bc2 = (const float*)d_in[11];
    float* out = (float*)d_out;

    cudaFuncSetAttribute(gemm_sk, cudaFuncAttributeMaxDynamicSharedMemorySize, SMEM_TOTAL);
    cudaFuncSetAttribute(heads_kernel, cudaFuncAttributeMaxDynamicSharedMemorySize,
                         2 * HEADS_G * HID * (int)sizeof(float));

    __half *xh, *w1h, *wc1h, *w2h, *h1h;
    float *partg;
    cudaGetSymbolAddress((void**)&xh,    g_xh);
    cudaGetSymbolAddress((void**)&w1h,   g_W1h);
    cudaGetSymbolAddress((void**)&wc1h,  g_Wc1h);
    cudaGetSymbolAddress((void**)&w2h,   g_W2h);
    cudaGetSymbolAddress((void**)&h1h,   g_h1h);
    cudaGetSymbolAddress((void**)&partg, g_part);

    // ---- fork: weight preps run on side stream, parallel with nchw+roi ----
    cudaEventRecord(g_ss.evFork, 0);
    cudaStreamWaitEvent(g_ss.s2, g_ss.evFork, 0);
    prep_big<<<dim3(16, 4, 98), 256, 0, g_ss.s2>>>(W1, Wc1);
    prep_w2 <<<dim3(16, 16), 256, 0, g_ss.s2>>>(W2);
    prep_heads<<<(4 * HID + NCLS * HID + 255) / 256, 256, 0, g_ss.s2>>>(W3, Wc2);
    cudaEventRecord(g_ss.evJoin, g_ss.s2);

    // ---- main stream: activations ----
    const int tot = N_IMG * H_F * W_F * C_CH;
    nchw2nhwc<<<(tot + 255) / 256, 256>>>(features);
    roi_align_kernel<<<NROI, 128>>>(proposals);

    // join: GEMM1 needs W1h/Wc1h (and later stages need W2h/W3t/Wc2t)
    cudaStreamWaitEvent(0, g_ss.evJoin, 0);

    // GEMM1, 128x128 tiles, z = zpart*2 + ks; slots 0,1 -> h1; 2,3 -> c
    gemm_sk<<<dim3(HID / BN, MPAD / BM, 4), 512, SMEM_TOTAL>>>(
        xh, w1h, wc1h, partg, KB, 2, (KB / 2) / BK);

    finalize1<<<(MPAD * HID / 4) / 256, 256>>>(b1, bc1);

    // GEMM2 split-K=4 (zpart always 0)
    gemm_sk<<<dim3(HID / BN, MPAD / BM, 4), 512, SMEM_TOTAL>>>(
        h1h, w2h, w2h, partg, HID, 4, (HID / 4) / BK);

    finalize2<<<(NROI * HID / 4 + 255) / 256, 256>>>(b2);

    heads_kernel<<<NROI / HEADS_G, 256, 2 * HEADS_G * HID * (int)sizeof(float)>>>(b3, bc2, out);
}

// round 15
// speedup vs baseline: 1.0212x; 1.0212x over previous
#include <cuda_runtime.h>
#include <cuda_fp16.h>
#include <cstdint>

// ---------------- problem constants ----------------
#define C_CH   256
#define H_F    50
#define W_F    50
#define N_IMG  2
#define NROI   1000
#define MPAD   1024
#define KB     12544          // 256*49
#define HID    1024
#define NCLS   81

// ---------------- scratch (device globals; no allocs) ----------------
__device__ __half  g_feath[N_IMG * H_F * W_F * C_CH];  // NHWC fp16
__device__ __half  g_xh  [MPAD * KB];                  // pooled x, fp16, [k][p*256+c]
__device__ __half  g_W1h [HID * KB];                   // fp16 [n][k], k-order = p*256+c
__device__ __half  g_Wc1h[HID * KB];
__device__ __half  g_W2h [HID * HID];                  // fp16 [n][k]
__device__ __half  g_h1h [MPAD * HID];                 // h1 fp16
__device__ float   g_part[4 * MPAD * HID];             // split-K fp32 partials (16 MB)
__device__ float   g_c  [NROI * HID];
__device__ float   g_h2 [NROI * HID];
__device__ float   g_W3t [4 * HID];
__device__ float   g_Wc2t[NCLS * HID];

// ---------------- streams/events (created pre-main, before harness checkpoints) ----------------
struct SideStream {
    cudaStream_t s2 = nullptr;
    cudaEvent_t  evFork = nullptr, evJoin = nullptr;
    SideStream() {
        cudaFree(0);   // establish context
        cudaStreamCreateWithFlags(&s2, cudaStreamNonBlocking);
        cudaEventCreateWithFlags(&evFork, cudaEventDisableTiming);
        cudaEventCreateWithFlags(&evJoin, cudaEventDisableTiming);
    }
};
static SideStream g_ss;

// ---------------- small PTX helpers ----------------
__device__ __forceinline__ uint32_t smem_u32(const void* p) {
    uint32_t a;
    asm("{ .reg .u64 t; cvta.to.shared.u64 t, %1; cvt.u32.u64 %0, t; }" : "=r"(a) : "l"(p));
    return a;
}
__device__ __forceinline__ void cp16(uint32_t d, const void* s) {
    asm volatile("cp.async.cg.shared.global [%0], [%1], 16;" :: "r"(d), "l"(s));
}
#define CP_COMMIT() asm volatile("cp.async.commit_group;" ::: "memory")
#define CP_WAIT2()  asm volatile("cp.async.wait_group 2;"  ::: "memory")

#define LDSM4(f, addr) \
    asm volatile("ldmatrix.sync.aligned.m8n8.x4.shared.b16 {%0,%1,%2,%3}, [%4];" \
        : "=r"((f)[0]), "=r"((f)[1]), "=r"((f)[2]), "=r"((f)[3]) : "r"(addr))

#define MMA16816(d, a, bl, bh) \
    asm volatile("mma.sync.aligned.m16n8k16.row.col.f32.f16.f16.f32 " \
        "{%0,%1,%2,%3},{%4,%5,%6,%7},{%8,%9},{%0,%1,%2,%3};" \
        : "+f"((d)[0]), "+f"((d)[1]), "+f"((d)[2]), "+f"((d)[3]) \
        : "r"((a)[0]), "r"((a)[1]), "r"((a)[2]), "r"((a)[3]), "r"(bl), "r"(bh))

// ---------------- 1) NCHW fp32 -> NHWC fp16 ----------------
__global__ void nchw2nhwc(const float* __restrict__ f) {
    int idx = blockIdx.x * 256 + threadIdx.x;
    const int total = N_IMG * H_F * W_F * C_CH;
    if (idx >= total) return;
    int c = idx & 255;
    int rest = idx >> 8;
    int w = rest % W_F; rest /= W_F;
    int h = rest % H_F;
    int n = rest / H_F;
    g_feath[idx] = __float2half_rn(f[((n * C_CH + c) * H_F + h) * W_F + w]);
}

// ---------------- 2) RoIAlign (fp16 gather) -> fp16 x ----------------
__global__ void roi_align_kernel(const float* __restrict__ props) {
    int k = blockIdx.x;
    int c = threadIdx.x;          // 0..127, channels 2c, 2c+1

    __shared__ int   s_i0y[14], s_i1y[14], s_i0x[14], s_i1x[14];
    __shared__ float s_wly[14], s_why[14], s_wlx[14], s_whx[14];
    __shared__ int   s_vy[14], s_vx[14];
    __shared__ int   s_b;

    if (c == 0) s_b = (int)props[k * 5];
    if (c < 28) {
        int axis = c / 14;
        int q    = c % 14;
        float lo = props[k * 5 + (axis ? 1 : 2)] * (1.0f / 16.0f);
        float hi = props[k * 5 + (axis ? 3 : 4)] * (1.0f / 16.0f);
        float ext = fmaxf(hi - lo, 1.0f);
        float bin = ext / 7.0f;
        int p = q >> 1, s = q & 1;
        float t = (float)p + ((float)s + 0.5f) * 0.5f;
        float y = lo + t * bin;
        int valid = (y > -1.0f) && (y < 50.0f);
        float yc = fminf(fmaxf(y, 0.0f), 49.0f);
        int i0 = (int)floorf(yc);
        int i1 = min(i0 + 1, 49);
        float whi = yc - (float)i0;
        float wlo = 1.0f - whi;
        if (axis == 0) { s_vy[q]=valid; s_i0y[q]=i0; s_i1y[q]=i1; s_wly[q]=wlo; s_why[q]=whi; }
        else           { s_vx[q]=valid; s_i0x[q]=i0; s_i1x[q]=i1; s_wlx[q]=wlo; s_whx[q]=whi; }
    }
    __syncthreads();

    const __half* F = g_feath + (size_t)s_b * (H_F * W_F * C_CH) + 2 * c;
    size_t ob = (size_t)k * KB + 2 * c;

    #pragma unroll 1
    for (int p = 0; p < 49; p++) {
        int by = p / 7, bx = p % 7;
        float ax = 0.0f, ay = 0.0f;
        #pragma unroll
        for (int sy = 0; sy < 2; sy++) {
            int qy = by * 2 + sy;
            if (!s_vy[qy]) continue;
            const __half* Fy0 = F + s_i0y[qy] * (W_F * C_CH);
            const __half* Fy1 = F + s_i1y[qy] * (W_F * C_CH);
            float wly = s_wly[qy], why = s_why[qy];
            #pragma unroll
            for (int sx = 0; sx < 2; sx++) {
                int qx = bx * 2 + sx;
                if (!s_vx[qx]) continue;
                int o0 = s_i0x[qx] * C_CH, o1 = s_i1x[qx] * C_CH;
                float2 f00 = __half22float2(*(const __half2*)(Fy0 + o0));
                float2 f01 = __half22float2(*(const __half2*)(Fy0 + o1));
                float2 f10 = __half22float2(*(const __half2*)(Fy1 + o0));
                float2 f11 = __half22float2(*(const __half2*)(Fy1 + o1));
                float wlx = s_wlx[qx], whx = s_whx[qx];
                ax += wly * (wlx * f00.x + whx * f01.x) + why * (wlx * f10.x + whx * f11.x);
                ay += wly * (wlx * f00.y + whx * f01.y) + why * (wlx * f10.y + whx * f11.y);
            }
        }
        *(__half2*)&g_xh[ob + (size_t)p * C_CH] = __floats2half2_rn(ax * 0.25f, ay * 0.25f);
    }
}

// ---------------- 3a) W1+Wc1 prep (fused): W[c*49+p][n] -> fp16 [n][p*256+c] ----------------
__global__ __launch_bounds__(256) void prep_big(const float* __restrict__ WA,
                                                const float* __restrict__ WB) {
    __shared__ float s[64][65];
    int zz = blockIdx.z;
    int p  = zz >> 1;
    const float* W = (zz & 1) ? WB : WA;
    __half* O = (zz & 1) ? g_Wc1h : g_W1h;
    int c0 = blockIdx.y << 6;
    int n0 = blockIdx.x << 6;
    for (int i = threadIdx.x; i < 4096; i += 256) {
        int ci = i >> 6, ni = i & 63;
        s[ci][ni] = W[(size_t)((c0 + ci) * 49 + p) * HID + n0 + ni];
    }
    __syncthreads();
    for (int i = threadIdx.x; i < 2048; i += 256) {
        int ni = i >> 5, c2 = (i & 31) * 2;
        __half2 hv = __floats2half2_rn(s[c2][ni], s[c2 + 1][ni]);
        *(__half2*)&O[(size_t)(n0 + ni) * KB + p * 256 + c0 + c2] = hv;
    }
}

// ---------------- 3b) W2 prep: W2[k][n] -> fp16 [n][k] ----------------
__global__ __launch_bounds__(256) void prep_w2(const float* __restrict__ W) {
    __shared__ float s[64][65];
    int k0 = blockIdx.y << 6;
    int n0 = blockIdx.x << 6;
    for (int i = threadIdx.x; i < 4096; i += 256) {
        int ki = i >> 6, ni = i & 63;
        s[ki][ni] = W[(size_t)(k0 + ki) * HID + n0 + ni];
    }
    __syncthreads();
    for (int i = threadIdx.x; i < 2048; i += 256) {
        int ni = i >> 5, k2 = (i & 31) * 2;
        __half2 hv = __floats2half2_rn(s[k2][ni], s[k2 + 1][ni]);
        *(__half2*)&g_W2h[(size_t)(n0 + ni) * HID + k0 + k2] = hv;
    }
}

// ---------------- 3c) head-weight transposes ----------------
__global__ void prep_heads(const float* __restrict__ W3, const float* __restrict__ Wc2) {
    int i = blockIdx.x * 256 + threadIdx.x;
    if (i < 4 * HID) {
        g_W3t[(i & 3) * HID + (i >> 2)] = W3[i];
    }
    int j = i - 4 * HID;
    if (j >= 0 && j < NCLS * HID) {
        g_Wc2t[(j % NCLS) * HID + (j / NCLS)] = Wc2[j];
    }
}

// ---------------- 4) split-K fp16 HMMA GEMM (fp32 partials out) ----------------
// CTA 128(M)x128(N), BK=32, 512 threads (16 warps, 4x4 grid, warp tile 32x32),
// 4-stage cp.async (82KB smem) -> 2 CTAs/SM = 32 warps/SM.  (R13-proven config)
#define BM 128
#define BN 128
#define BK 32
#define NSTAGE 4
#define ROWB 80                          // 64B data + 16B pad
#define A_TILE (128 * ROWB)              // 10240
#define B_OFF  A_TILE
#define STAGE_BYTES (256 * ROWB)         // 20480
#define SMEM_TOTAL (NSTAGE * STAGE_BYTES)    // 81920

__global__ void __launch_bounds__(512, 2) gemm_sk(
    const __half* __restrict__ A,
    const __half* __restrict__ Ba, const __half* __restrict__ Bb,
    float* __restrict__ part,
    int K, int nsplit, int chunks_per_split)
{
    extern __shared__ char sm[];
    const int tid  = threadIdx.x;
    const int lane = tid & 31;
    const int wid  = tid >> 5;
    const int warp_m = wid & 3;          // 0..3  (32-row slabs)
    const int warp_n = wid >> 2;         // 0..3  (32-col slabs)
    const int row0 = blockIdx.y * BM;
    const int col0 = blockIdx.x * BN;
    const int zpart = blockIdx.z / nsplit;
    const int ks    = blockIdx.z - zpart * nsplit;
    const int chunk0 = ks * chunks_per_split;

    const __half* B = zpart ? Bb : Ba;
    float* pout = part + (size_t)blockIdx.z * (MPAD * HID);

    const uint32_t sbase = smem_u32(sm);
    const int nch = chunks_per_split;

    // cp.async: threads 0..255 load A, 256..511 load B.
    const int halfsel = tid >> 8;                 // 0 = A, 1 = B
    const int lr = (tid & 255) >> 1;
    const int lc = (tid & 1) * 32;
    const __half* gsrcm = halfsel ? (B + (size_t)(col0 + lr) * K)
                                  : (A + (size_t)(row0 + lr) * K);
    const char* gsrc = (const char*)gsrcm + lc;
    const uint32_t sdst = sbase + halfsel * A_TILE + lr * ROWB + lc;

    #define ISSUE(st, kc) do {                                        \
        size_t go = (size_t)(chunk0 + (kc)) * (BK * 2);                \
        uint32_t dd = sdst + (st) * STAGE_BYTES;                       \
        const char* pp = gsrc + go;                                    \
        cp16(dd,      pp);                                             \
        cp16(dd + 16, pp + 16);                                        \
        CP_COMMIT();                                                   \
    } while (0)

    ISSUE(0, 0); ISSUE(1, 1); ISSUE(2, 2);

    float acc[2][4][4] = {};
    const uint32_t lrow = (lane & 15) * ROWB + ((lane >> 4) * 16);

    for (int kc = 0; kc < nch; kc++) {
        CP_WAIT2();
        __syncthreads();

        if (kc + 3 < nch) {
            ISSUE((kc + 3) & (NSTAGE - 1), kc + 3);
        } else {
            CP_COMMIT();   // keep group accounting uniform for CP_WAIT2
        }

        const int st = kc & (NSTAGE - 1);
        const uint32_t sAh = sbase + st * STAGE_BYTES + (warp_m * 32) * ROWB + lrow;
        const uint32_t sBs = sbase + st * STAGE_BYTES + B_OFF + (warp_n * 32) * ROWB + lrow;

        #pragma unroll
        for (int ksi = 0; ksi < 2; ksi++) {
            uint32_t af[2][4], bf[2][4];
            LDSM4(af[0], sAh + ksi * 32);
            LDSM4(af[1], sAh + 16 * ROWB + ksi * 32);
            LDSM4(bf[0], sBs + ksi * 32);
            LDSM4(bf[1], sBs + 16 * ROWB + ksi * 32);
            #pragma unroll
            for (int mt = 0; mt < 2; mt++)
                #pragma unroll
                for (int nt = 0; nt < 4; nt++)
                    MMA16816(acc[mt][nt], af[mt],
                             bf[nt >> 1][nt & 1], bf[nt >> 1][(nt & 1) + 2]);
        }
    }

    // ---------------- epilogue: raw fp32 partials ----------------
    #pragma unroll
    for (int mt = 0; mt < 2; mt++) {
        #pragma unroll
        for (int half = 0; half < 2; half++) {
            int r = row0 + warp_m * 32 + mt * 16 + (lane >> 2) + half * 8;
            #pragma unroll
            for (int nt = 0; nt < 4; nt++) {
                int ccol = col0 + warp_n * 32 + nt * 8 + (lane & 3) * 2;
                float2 v = make_float2(acc[mt][nt][half * 2 + 0],
                                       acc[mt][nt][half * 2 + 1]);
                *(float2*)&pout[(size_t)r * HID + ccol] = v;
            }
        }
    }
    #undef ISSUE
}

// ---------------- 4b) finalize GEMM1: h1 = relu(p0+p1+b1) fp16; c = relu(p2+p3+bc1) f32 ----------------
__global__ __launch_bounds__(256) void finalize1(const float* __restrict__ b1,
                                                 const float* __restrict__ bc1) {
    int idx4 = blockIdx.x * 256 + threadIdx.x;      // 1M/4 = 262144 idx4
    int base = idx4 * 4;
    int m = base >> 10;
    int n = base & 1023;
    const float* p = g_part;
    float4 p0 = *(const float4*)&p[0 * MPAD * HID + base];
    float4 p1 = *(const float4*)&p[1 * MPAD * HID + base];
    float4 bb = *(const float4*)&b1[n];
    float4 h;
    h.x = fmaxf(p0.x + p1.x + bb.x, 0.0f);
    h.y = fmaxf(p0.y + p1.y + bb.y, 0.0f);
    h.z = fmaxf(p0.z + p1.z + bb.z, 0.0f);
    h.w = fmaxf(p0.w + p1.w + bb.w, 0.0f);
    __half2 o0 = __floats2half2_rn(h.x, h.y);
    __half2 o1 = __floats2half2_rn(h.z, h.w);
    *(__half2*)&g_h1h[base]     = o0;
    *(__half2*)&g_h1h[base + 2] = o1;

    if (m < NROI) {
        float4 p2 = *(const float4*)&p[2 * MPAD * HID + base];
        float4 p3 = *(const float4*)&p[3 * MPAD * HID + base];
        float4 bc = *(const float4*)&bc1[n];
        float4 cv;
        cv.x = fmaxf(p2.x + p3.x + bc.x, 0.0f);
        cv.y = fmaxf(p2.y + p3.y + bc.y, 0.0f);
        cv.z = fmaxf(p2.z + p3.z + bc.z, 0.0f);
        cv.w = fmaxf(p2.w + p3.w + bc.w, 0.0f);
        *(float4*)&g_c[base] = cv;
    }
}

// ---------------- 4c) finalize GEMM2: h2 = relu(p0+p1+p2+p3+b2) f32 (rows < NROI) ----------------
__global__ __launch_bounds__(256) void finalize2(const float* __restrict__ b2) {
    int idx4 = blockIdx.x * 256 + threadIdx.x;      // over NROI*HID/4
    int base = idx4 * 4;
    if (base >= NROI * HID) return;
    int n = base & 1023;
    const float* p = g_part;
    float4 p0 = *(const float4*)&p[0 * MPAD * HID + base];
    float4 p1 = *(const float4*)&p[1 * MPAD * HID + base];
    float4 p2 = *(const float4*)&p[2 * MPAD * HID + base];
    float4 p3 = *(const float4*)&p[3 * MPAD * HID + base];
    float4 bb = *(const float4*)&b2[n];
    float4 h;
    h.x = fmaxf(p0.x + p1.x + p2.x + p3.x + bb.x, 0.0f);
    h.y = fmaxf(p0.y + p1.y + p2.y + p3.y + bb.y, 0.0f);
    h.z = fmaxf(p0.z + p1.z + p2.z + p3.z + bb.z, 0.0f);
    h.w = fmaxf(p0.w + p1.w + p2.w + p3.w + bb.w, 0.0f);
    *(float4*)&g_h2[base] = h;
}

// ---------------- 5) heads: 8 rois per block, weight rows shared ----------------
#define HEADS_G 8
__global__ void heads_kernel(const float* __restrict__ b3, const float* __restrict__ bc2,
                             float* __restrict__ out)
{
    extern __shared__ float s[];          // [8*1024 h2 | 8*1024 c]
    float* sh = s;
    float* sc = s + HEADS_G * HID;
    int g0 = blockIdx.x * HEADS_G;
    int lane = threadIdx.x & 31;
    int wid  = threadIdx.x >> 5;          // 8 warps

    for (int i = threadIdx.x; i < HEADS_G * HID; i += blockDim.x) {
        int r = g0 + (i >> 10), kk = i & 1023;
        sh[i] = g_h2[(size_t)r * HID + kk];
        sc[i] = g_c [(size_t)r * HID + kk];
    }
    __syncthreads();

    for (int j = wid; j < 4 + NCLS; j += 8) {
        const float* wrow;
        const float* src;
        float bv;
        if (j < 4) { wrow = g_W3t  + (size_t)j * HID;       src = sh; bv = b3[j]; }
        else       { wrow = g_Wc2t + (size_t)(j - 4) * HID; src = sc; bv = bc2[j - 4]; }
        float a[HEADS_G] = {};
        for (int kk = lane; kk < HID; kk += 32) {
            float wv = wrow[kk];
            #pragma unroll
            for (int g = 0; g < HEADS_G; g++)
                a[g] += src[g * HID + kk] * wv;
        }
        #pragma unroll
        for (int g = 0; g < HEADS_G; g++) {
            #pragma unroll
            for (int o = 16; o > 0; o >>= 1) a[g] += __shfl_xor_sync(0xFFFFFFFFu, a[g], o);
        }
        if (lane == 0) {
            #pragma unroll
            for (int g = 0; g < HEADS_G; g++) {
                int k = g0 + g;
                if (j < 4) out[k * 4 + j] = a[g] + bv;
                else       out[NROI * 4 + k * NCLS + (j - 4)] = a[g] + bv;
            }
        }
    }
}

// ---------------- launch ----------------
extern "C" void kernel_launch(void* const* d_in, const int* in_sizes, int n_in,
                              void* d_out, int out_size)
{
    const float* features  = (const float*)d_in[0];
    const float* proposals = (const float*)d_in[1];
    const float* W1  = (const float*)d_in[2];
    const float* b1  = (const float*)d_in[3];
    const float* W2  = (const float*)d_in[4];
    const float* b2  = (const float*)d_in[5];
    const float* W3  = (const float*)d_in[6];
    const float* b3  = (const float*)d_in[7];
    const float* Wc1 = (const float*)d_in[8];
    const float* bc1 = (const float*)d_in[9];
    const float* Wc2 = (const float*)d_in[10];
    const float* bc2 = (const float*)d_in[11];
    float* out = (float*)d_out;

    cudaFuncSetAttribute(gemm_sk, cudaFuncAttributeMaxDynamicSharedMemorySize, SMEM_TOTAL);
    cudaFuncSetAttribute(heads_kernel, cudaFuncAttributeMaxDynamicSharedMemorySize,
                         2 * HEADS_G * HID * (int)sizeof(float));

    __half *xh, *w1h, *wc1h, *w2h, *h1h;
    float *partg;
    cudaGetSymbolAddress((void**)&xh,    g_xh);
    cudaGetSymbolAddress((void**)&w1h,   g_W1h);
    cudaGetSymbolAddress((void**)&wc1h,  g_Wc1h);
    cudaGetSymbolAddress((void**)&w2h,   g_W2h);
    cudaGetSymbolAddress((void**)&h1h,   g_h1h);
    cudaGetSymbolAddress((void**)&partg, g_part);

    // ---- fork: weight preps run on side stream, parallel with nchw+roi ----
    cudaEventRecord(g_ss.evFork, 0);
    cudaStreamWaitEvent(g_ss.s2, g_ss.evFork, 0);
    prep_big<<<dim3(16, 4, 98), 256, 0, g_ss.s2>>>(W1, Wc1);
    prep_w2 <<<dim3(16, 16), 256, 0, g_ss.s2>>>(W2);
    prep_heads<<<(4 * HID + NCLS * HID + 255) / 256, 256, 0, g_ss.s2>>>(W3, Wc2);
    cudaEventRecord(g_ss.evJoin, g_ss.s2);

    // ---- main stream: activations ----
    const int tot = N_IMG * H_F * W_F * C_CH;
    nchw2nhwc<<<(tot + 255) / 256, 256>>>(features);
    roi_align_kernel<<<NROI, 128>>>(proposals);

    // join: GEMM1 needs W1h/Wc1h (later stages need W2h/W3t/Wc2t)
    cudaStreamWaitEvent(0, g_ss.evJoin, 0);

    // GEMM1, 128x128 tiles (R13 config), z = zpart*2 + ks; slots 0,1 -> h1; 2,3 -> c
    gemm_sk<<<dim3(HID / BN, MPAD / BM, 4), 512, SMEM_TOTAL>>>(
        xh, w1h, wc1h, partg, KB, 2, (KB / 2) / BK);

    finalize1<<<(MPAD * HID / 4) / 256, 256>>>(b1, bc1);

    // GEMM2 split-K=4 (zpart always 0)
    gemm_sk<<<dim3(HID / BN, MPAD / BM, 4), 512, SMEM_TOTAL>>>(
        h1h, w2h, w2h, partg, HID, 4, (HID / 4) / BK);

    finalize2<<<(NROI * HID / 4 + 255) / 256, 256>>>(b2);

    heads_kernel<<<NROI / HEADS_G, 256, 2 * HEADS_G * HID * (int)sizeof(float)>>>(b3, bc2, out);
}

// round 16
// speedup vs baseline: 1.0423x; 1.0207x over previous
#include <cuda_runtime.h>
#include <cuda_fp16.h>
#include <cstdint>

// ---------------- problem constants ----------------
#define C_CH   256
#define H_F    50
#define W_F    50
#define N_IMG  2
#define NROI   1000
#define MPAD   1024
#define KB     12544          // 256*49
#define HID    1024
#define NCLS   81

// ---------------- scratch (device globals; no allocs) ----------------
__device__ __half  g_feath[N_IMG * H_F * W_F * C_CH];  // NHWC fp16
__device__ __half  g_xh  [MPAD * KB];                  // pooled x, fp16, [k][p*256+c]
__device__ __half  g_W1h [HID * KB];                   // fp16 [n][k], k-order = p*256+c
__device__ __half  g_Wc1h[HID * KB];
__device__ __half  g_W2h [HID * HID];                  // fp16 [n][k]
__device__ __half  g_h1h [MPAD * HID];                 // h1 fp16
__device__ float   g_part[8 * MPAD * HID];             // split-K fp32 partials (32 MB)
__device__ float   g_c  [NROI * HID];
__device__ float   g_h2 [NROI * HID];
__device__ float   g_W3t [4 * HID];
__device__ float   g_Wc2t[NCLS * HID];

// ---------------- streams/events (created pre-main, before harness checkpoints) ----------------
struct SideStream {
    cudaStream_t s2 = nullptr;
    cudaEvent_t  evFork = nullptr, evJoin1 = nullptr, evJoin2 = nullptr;
    SideStream() {
        cudaFree(0);   // establish context
        cudaStreamCreateWithFlags(&s2, cudaStreamNonBlocking);
        cudaEventCreateWithFlags(&evFork,  cudaEventDisableTiming);
        cudaEventCreateWithFlags(&evJoin1, cudaEventDisableTiming);
        cudaEventCreateWithFlags(&evJoin2, cudaEventDisableTiming);
    }
};
static SideStream g_ss;

// ---------------- small PTX helpers ----------------
__device__ __forceinline__ uint32_t smem_u32(const void* p) {
    uint32_t a;
    asm("{ .reg .u64 t; cvta.to.shared.u64 t, %1; cvt.u32.u64 %0, t; }" : "=r"(a) : "l"(p));
    return a;
}
__device__ __forceinline__ void cp16(uint32_t d, const void* s) {
    asm volatile("cp.async.cg.shared.global [%0], [%1], 16;" :: "r"(d), "l"(s));
}
#define CP_COMMIT() asm volatile("cp.async.commit_group;" ::: "memory")
#define CP_WAIT2()  asm volatile("cp.async.wait_group 2;"  ::: "memory")

#define LDSM4(f, addr) \
    asm volatile("ldmatrix.sync.aligned.m8n8.x4.shared.b16 {%0,%1,%2,%3}, [%4];" \
        : "=r"((f)[0]), "=r"((f)[1]), "=r"((f)[2]), "=r"((f)[3]) : "r"(addr))

#define MMA16816(d, a, bl, bh) \
    asm volatile("mma.sync.aligned.m16n8k16.row.col.f32.f16.f16.f32 " \
        "{%0,%1,%2,%3},{%4,%5,%6,%7},{%8,%9},{%0,%1,%2,%3};" \
        : "+f"((d)[0]), "+f"((d)[1]), "+f"((d)[2]), "+f"((d)[3]) \
        : "r"((a)[0]), "r"((a)[1]), "r"((a)[2]), "r"((a)[3]), "r"(bl), "r"(bh))

// ---------------- 1) NCHW fp32 -> NHWC fp16 ----------------
__global__ void nchw2nhwc(const float* __restrict__ f) {
    int idx = blockIdx.x * 256 + threadIdx.x;
    const int total = N_IMG * H_F * W_F * C_CH;
    if (idx >= total) return;
    int c = idx & 255;
    int rest = idx >> 8;
    int w = rest % W_F; rest /= W_F;
    int h = rest % H_F;
    int n = rest / H_F;
    g_feath[idx] = __float2half_rn(f[((n * C_CH + c) * H_F + h) * W_F + w]);
}

// ---------------- 2) RoIAlign (fp16 gather) -> fp16 x ----------------
// 256 threads: tid>>7 selects even/odd bins (p), tid&127 = channel pair.
__global__ void roi_align_kernel(const float* __restrict__ props) {
    int k = blockIdx.x;
    int tid = threadIdx.x;
    int sub = tid >> 7;           // 0: even p, 1: odd p
    int c   = tid & 127;          // channels 2c, 2c+1

    __shared__ int   s_i0y[14], s_i1y[14], s_i0x[14], s_i1x[14];
    __shared__ float s_wly[14], s_why[14], s_wlx[14], s_whx[14];
    __shared__ int   s_vy[14], s_vx[14];
    __shared__ int   s_b;

    if (tid == 0) s_b = (int)props[k * 5];
    if (tid < 28) {
        int axis = tid / 14;
        int q    = tid % 14;
        float lo = props[k * 5 + (axis ? 1 : 2)] * (1.0f / 16.0f);
        float hi = props[k * 5 + (axis ? 3 : 4)] * (1.0f / 16.0f);
        float ext = fmaxf(hi - lo, 1.0f);
        float bin = ext / 7.0f;
        int p = q >> 1, s = q & 1;
        float t = (float)p + ((float)s + 0.5f) * 0.5f;
        float y = lo + t * bin;
        int valid = (y > -1.0f) && (y < 50.0f);
        float yc = fminf(fmaxf(y, 0.0f), 49.0f);
        int i0 = (int)floorf(yc);
        int i1 = min(i0 + 1, 49);
        float whi = yc - (float)i0;
        float wlo = 1.0f - whi;
        if (axis == 0) { s_vy[q]=valid; s_i0y[q]=i0; s_i1y[q]=i1; s_wly[q]=wlo; s_why[q]=whi; }
        else           { s_vx[q]=valid; s_i0x[q]=i0; s_i1x[q]=i1; s_wlx[q]=wlo; s_whx[q]=whi; }
    }
    __syncthreads();

    const __half* F = g_feath + (size_t)s_b * (H_F * W_F * C_CH) + 2 * c;
    size_t ob = (size_t)k * KB + 2 * c;

    #pragma unroll 1
    for (int p = sub; p < 49; p += 2) {
        int by = p / 7, bx = p % 7;
        float ax = 0.0f, ay = 0.0f;
        #pragma unroll
        for (int sy = 0; sy < 2; sy++) {
            int qy = by * 2 + sy;
            if (!s_vy[qy]) continue;
            const __half* Fy0 = F + s_i0y[qy] * (W_F * C_CH);
            const __half* Fy1 = F + s_i1y[qy] * (W_F * C_CH);
            float wly = s_wly[qy], why = s_why[qy];
            #pragma unroll
            for (int sx = 0; sx < 2; sx++) {
                int qx = bx * 2 + sx;
                if (!s_vx[qx]) continue;
                int o0 = s_i0x[qx] * C_CH, o1 = s_i1x[qx] * C_CH;
                float2 f00 = __half22float2(*(const __half2*)(Fy0 + o0));
                float2 f01 = __half22float2(*(const __half2*)(Fy0 + o1));
                float2 f10 = __half22float2(*(const __half2*)(Fy1 + o0));
                float2 f11 = __half22float2(*(const __half2*)(Fy1 + o1));
                float wlx = s_wlx[qx], whx = s_whx[qx];
                ax += wly * (wlx * f00.x + whx * f01.x) + why * (wlx * f10.x + whx * f11.x);
                ay += wly * (wlx * f00.y + whx * f01.y) + why * (wlx * f10.y + whx * f11.y);
            }
        }
        *(__half2*)&g_xh[ob + (size_t)p * C_CH] = __floats2half2_rn(ax * 0.25f, ay * 0.25f);
    }
}

// ---------------- 3a) W1+Wc1 prep (fused): W[c*49+p][n] -> fp16 [n][p*256+c] ----------------
__global__ __launch_bounds__(256) void prep_big(const float* __restrict__ WA,
                                                const float* __restrict__ WB) {
    __shared__ float s[64][65];
    int zz = blockIdx.z;
    int p  = zz >> 1;
    const float* W = (zz & 1) ? WB : WA;
    __half* O = (zz & 1) ? g_Wc1h : g_W1h;
    int c0 = blockIdx.y << 6;
    int n0 = blockIdx.x << 6;
    for (int i = threadIdx.x; i < 4096; i += 256) {
        int ci = i >> 6, ni = i & 63;
        s[ci][ni] = W[(size_t)((c0 + ci) * 49 + p) * HID + n0 + ni];
    }
    __syncthreads();
    for (int i = threadIdx.x; i < 2048; i += 256) {
        int ni = i >> 5, c2 = (i & 31) * 2;
        __half2 hv = __floats2half2_rn(s[c2][ni], s[c2 + 1][ni]);
        *(__half2*)&O[(size_t)(n0 + ni) * KB + p * 256 + c0 + c2] = hv;
    }
}

// ---------------- 3b) W2 prep: W2[k][n] -> fp16 [n][k] ----------------
__global__ __launch_bounds__(256) void prep_w2(const float* __restrict__ W) {
    __shared__ float s[64][65];
    int k0 = blockIdx.y << 6;
    int n0 = blockIdx.x << 6;
    for (int i = threadIdx.x; i < 4096; i += 256) {
        int ki = i >> 6, ni = i & 63;
        s[ki][ni] = W[(size_t)(k0 + ki) * HID + n0 + ni];
    }
    __syncthreads();
    for (int i = threadIdx.x; i < 2048; i += 256) {
        int ni = i >> 5, k2 = (i & 31) * 2;
        __half2 hv = __floats2half2_rn(s[k2][ni], s[k2 + 1][ni]);
        *(__half2*)&g_W2h[(size_t)(n0 + ni) * HID + k0 + k2] = hv;
    }
}

// ---------------- 3c) head-weight transposes ----------------
__global__ void prep_heads(const float* __restrict__ W3, const float* __restrict__ Wc2) {
    int i = blockIdx.x * 256 + threadIdx.x;
    if (i < 4 * HID) {
        g_W3t[(i & 3) * HID + (i >> 2)] = W3[i];
    }
    int j = i - 4 * HID;
    if (j >= 0 && j < NCLS * HID) {
        g_Wc2t[(j % NCLS) * HID + (j / NCLS)] = Wc2[j];
    }
}

// ---------------- 4) split-K fp16 HMMA GEMM (fp32 partials out) ----------------
// CTA 128(M)x128(N), BK=32, 512 threads (16 warps, 4x4 grid, warp tile 32x32),
// 4-stage cp.async (82KB smem) -> 2 CTAs/SM = 32 warps/SM.  (R13-proven config)
#define BM 128
#define BN 128
#define BK 32
#define NSTAGE 4
#define ROWB 80                          // 64B data + 16B pad
#define A_TILE (128 * ROWB)              // 10240
#define B_OFF  A_TILE
#define STAGE_BYTES (256 * ROWB)         // 20480
#define SMEM_TOTAL (NSTAGE * STAGE_BYTES)    // 81920

__global__ void __launch_bounds__(512, 2) gemm_sk(
    const __half* __restrict__ A,
    const __half* __restrict__ Ba, const __half* __restrict__ Bb,
    float* __restrict__ part,
    int K, int nsplit, int chunks_per_split)
{
    extern __shared__ char sm[];
    const int tid  = threadIdx.x;
    const int lane = tid & 31;
    const int wid  = tid >> 5;
    const int warp_m = wid & 3;          // 0..3  (32-row slabs)
    const int warp_n = wid >> 2;         // 0..3  (32-col slabs)
    const int row0 = blockIdx.y * BM;
    const int col0 = blockIdx.x * BN;
    const int zpart = blockIdx.z / nsplit;
    const int ks    = blockIdx.z - zpart * nsplit;
    const int chunk0 = ks * chunks_per_split;

    const __half* B = zpart ? Bb : Ba;
    float* pout = part + (size_t)blockIdx.z * (MPAD * HID);

    const uint32_t sbase = smem_u32(sm);
    const int nch = chunks_per_split;

    // cp.async: threads 0..255 load A, 256..511 load B.
    const int halfsel = tid >> 8;                 // 0 = A, 1 = B
    const int lr = (tid & 255) >> 1;
    const int lc = (tid & 1) * 32;
    const __half* gsrcm = halfsel ? (B + (size_t)(col0 + lr) * K)
                                  : (A + (size_t)(row0 + lr) * K);
    const char* gsrc = (const char*)gsrcm + lc;
    const uint32_t sdst = sbase + halfsel * A_TILE + lr * ROWB + lc;

    #define ISSUE(st, kc) do {                                        \
        size_t go = (size_t)(chunk0 + (kc)) * (BK * 2);                \
        uint32_t dd = sdst + (st) * STAGE_BYTES;                       \
        const char* pp = gsrc + go;                                    \
        cp16(dd,      pp);                                             \
        cp16(dd + 16, pp + 16);                                        \
        CP_COMMIT();                                                   \
    } while (0)

    ISSUE(0, 0); ISSUE(1, 1); ISSUE(2, 2);

    float acc[2][4][4] = {};
    const uint32_t lrow = (lane & 15) * ROWB + ((lane >> 4) * 16);

    for (int kc = 0; kc < nch; kc++) {
        CP_WAIT2();
        __syncthreads();

        if (kc + 3 < nch) {
            ISSUE((kc + 3) & (NSTAGE - 1), kc + 3);
        } else {
            CP_COMMIT();   // keep group accounting uniform for CP_WAIT2
        }

        const int st = kc & (NSTAGE - 1);
        const uint32_t sAh = sbase + st * STAGE_BYTES + (warp_m * 32) * ROWB + lrow;
        const uint32_t sBs = sbase + st * STAGE_BYTES + B_OFF + (warp_n * 32) * ROWB + lrow;

        #pragma unroll
        for (int ksi = 0; ksi < 2; ksi++) {
            uint32_t af[2][4], bf[2][4];
            LDSM4(af[0], sAh + ksi * 32);
            LDSM4(af[1], sAh + 16 * ROWB + ksi * 32);
            LDSM4(bf[0], sBs + ksi * 32);
            LDSM4(bf[1], sBs + 16 * ROWB + ksi * 32);
            #pragma unroll
            for (int mt = 0; mt < 2; mt++)
                #pragma unroll
                for (int nt = 0; nt < 4; nt++)
                    MMA16816(acc[mt][nt], af[mt],
                             bf[nt >> 1][nt & 1], bf[nt >> 1][(nt & 1) + 2]);
        }
    }

    // ---------------- epilogue: raw fp32 partials ----------------
    #pragma unroll
    for (int mt = 0; mt < 2; mt++) {
        #pragma unroll
        for (int half = 0; half < 2; half++) {
            int r = row0 + warp_m * 32 + mt * 16 + (lane >> 2) + half * 8;
            #pragma unroll
            for (int nt = 0; nt < 4; nt++) {
                int ccol = col0 + warp_n * 32 + nt * 8 + (lane & 3) * 2;
                float2 v = make_float2(acc[mt][nt][half * 2 + 0],
                                       acc[mt][nt][half * 2 + 1]);
                *(float2*)&pout[(size_t)r * HID + ccol] = v;
            }
        }
    }
    #undef ISSUE
}

// ---------------- 4b) finalize GEMM1: h1 = relu(p0+p1+b1) fp16; c = relu(p2+p3+bc1) f32 ----------------
__global__ __launch_bounds__(256) void finalize1(const float* __restrict__ b1,
                                                 const float* __restrict__ bc1) {
    int idx4 = blockIdx.x * 256 + threadIdx.x;      // 1M/4 = 262144 idx4
    int base = idx4 * 4;
    int m = base >> 10;
    int n = base & 1023;
    const float* p = g_part;
    float4 p0 = *(const float4*)&p[0 * MPAD * HID + base];
    float4 p1 = *(const float4*)&p[1 * MPAD * HID + base];
    float4 bb = *(const float4*)&b1[n];
    float4 h;
    h.x = fmaxf(p0.x + p1.x + bb.x, 0.0f);
    h.y = fmaxf(p0.y + p1.y + bb.y, 0.0f);
    h.z = fmaxf(p0.z + p1.z + bb.z, 0.0f);
    h.w = fmaxf(p0.w + p1.w + bb.w, 0.0f);
    __half2 o0 = __floats2half2_rn(h.x, h.y);
    __half2 o1 = __floats2half2_rn(h.z, h.w);
    *(__half2*)&g_h1h[base]     = o0;
    *(__half2*)&g_h1h[base + 2] = o1;

    if (m < NROI) {
        float4 p2 = *(const float4*)&p[2 * MPAD * HID + base];
        float4 p3 = *(const float4*)&p[3 * MPAD * HID + base];
        float4 bc = *(const float4*)&bc1[n];
        float4 cv;
        cv.x = fmaxf(p2.x + p3.x + bc.x, 0.0f);
        cv.y = fmaxf(p2.y + p3.y + bc.y, 0.0f);
        cv.z = fmaxf(p2.z + p3.z + bc.z, 0.0f);
        cv.w = fmaxf(p2.w + p3.w + bc.w, 0.0f);
        *(float4*)&g_c[base] = cv;
    }
}

// ---------------- 4c) finalize GEMM2: h2 = relu(sum p0..p7 + b2) f32 (rows < NROI) ----------------
__global__ __launch_bounds__(256) void finalize2(const float* __restrict__ b2) {
    int idx4 = blockIdx.x * 256 + threadIdx.x;      // over NROI*HID/4
    int base = idx4 * 4;
    if (base >= NROI * HID) return;
    int n = base & 1023;
    const float* p = g_part;
    float4 acc = *(const float4*)&b2[n];
    #pragma unroll
    for (int s = 0; s < 8; s++) {
        float4 ps = *(const float4*)&p[(size_t)s * MPAD * HID + base];
        acc.x += ps.x; acc.y += ps.y; acc.z += ps.z; acc.w += ps.w;
    }
    float4 h;
    h.x = fmaxf(acc.x, 0.0f);
    h.y = fmaxf(acc.y, 0.0f);
    h.z = fmaxf(acc.z, 0.0f);
    h.w = fmaxf(acc.w, 0.0f);
    *(float4*)&g_h2[base] = h;
}

// ---------------- 5) heads: 8 rois per block, weight rows shared ----------------
#define HEADS_G 8
__global__ void heads_kernel(const float* __restrict__ b3, const float* __restrict__ bc2,
                             float* __restrict__ out)
{
    extern __shared__ float s[];          // [8*1024 h2 | 8*1024 c]
    float* sh = s;
    float* sc = s + HEADS_G * HID;
    int g0 = blockIdx.x * HEADS_G;
    int lane = threadIdx.x & 31;
    int wid  = threadIdx.x >> 5;          // 8 warps

    for (int i = threadIdx.x; i < HEADS_G * HID; i += blockDim.x) {
        int r = g0 + (i >> 10), kk = i & 1023;
        sh[i] = g_h2[(size_t)r * HID + kk];
        sc[i] = g_c [(size_t)r * HID + kk];
    }
    __syncthreads();

    for (int j = wid; j < 4 + NCLS; j += 8) {
        const float* wrow;
        const float* src;
        float bv;
        if (j < 4) { wrow = g_W3t  + (size_t)j * HID;       src = sh; bv = b3[j]; }
        else       { wrow = g_Wc2t + (size_t)(j - 4) * HID; src = sc; bv = bc2[j - 4]; }
        float a[HEADS_G] = {};
        for (int kk = lane; kk < HID; kk += 32) {
            float wv = wrow[kk];
            #pragma unroll
            for (int g = 0; g < HEADS_G; g++)
                a[g] += src[g * HID + kk] * wv;
        }
        #pragma unroll
        for (int g = 0; g < HEADS_G; g++) {
            #pragma unroll
            for (int o = 16; o > 0; o >>= 1) a[g] += __shfl_xor_sync(0xFFFFFFFFu, a[g], o);
        }
        if (lane == 0) {
            #pragma unroll
            for (int g = 0; g < HEADS_G; g++) {
                int k = g0 + g;
                if (j < 4) out[k * 4 + j] = a[g] + bv;
                else       out[NROI * 4 + k * NCLS + (j - 4)] = a[g] + bv;
            }
        }
    }
}

// ---------------- launch ----------------
extern "C" void kernel_launch(void* const* d_in, const int* in_sizes, int n_in,
                              void* d_out, int out_size)
{
    const float* features  = (const float*)d_in[0];
    const float* proposals = (const float*)d_in[1];
    const float* W1  = (const float*)d_in[2];
    const float* b1  = (const float*)d_in[3];
    const float* W2  = (const float*)d_in[4];
    const float* b2  = (const float*)d_in[5];
    const float* W3  = (const float*)d_in[6];
    const float* b3  = (const float*)d_in[7];
    const float* Wc1 = (const float*)d_in[8];
    const float* bc1 = (const float*)d_in[9];
    const float* Wc2 = (const float*)d_in[10];
    const float* bc2 = (const float*)d_in[11];
    float* out = (float*)d_out;

    cudaFuncSetAttribute(gemm_sk, cudaFuncAttributeMaxDynamicSharedMemorySize, SMEM_TOTAL);
    cudaFuncSetAttribute(heads_kernel, cudaFuncAttributeMaxDynamicSharedMemorySize,
                         2 * HEADS_G * HID * (int)sizeof(float));

    __half *xh, *w1h, *wc1h, *w2h, *h1h;
    float *partg;
    cudaGetSymbolAddress((void**)&xh,    g_xh);
    cudaGetSymbolAddress((void**)&w1h,   g_W1h);
    cudaGetSymbolAddress((void**)&wc1h,  g_Wc1h);
    cudaGetSymbolAddress((void**)&w2h,   g_W2h);
    cudaGetSymbolAddress((void**)&h1h,   g_h1h);
    cudaGetSymbolAddress((void**)&partg, g_part);

    // ---- fork: prep_big runs beside nchw+roi; w2/heads preps overlap GEMM1 ----
    cudaEventRecord(g_ss.evFork, 0);
    cudaStreamWaitEvent(g_ss.s2, g_ss.evFork, 0);
    prep_big<<<dim3(16, 4, 98), 256, 0, g_ss.s2>>>(W1, Wc1);
    cudaEventRecord(g_ss.evJoin1, g_ss.s2);
    prep_w2 <<<dim3(16, 16), 256, 0, g_ss.s2>>>(W2);
    prep_heads<<<(4 * HID + NCLS * HID + 255) / 256, 256, 0, g_ss.s2>>>(W3, Wc2);
    cudaEventRecord(g_ss.evJoin2, g_ss.s2);

    // ---- main stream: activations ----
    const int tot = N_IMG * H_F * W_F * C_CH;
    nchw2nhwc<<<(tot + 255) / 256, 256>>>(features);
    roi_align_kernel<<<NROI, 256>>>(proposals);

    // join 1: GEMM1 needs only W1h/Wc1h
    cudaStreamWaitEvent(0, g_ss.evJoin1, 0);

    // GEMM1, 128x128 tiles (R13 config), z = zpart*2 + ks; slots 0,1 -> h1; 2,3 -> c
    gemm_sk<<<dim3(HID / BN, MPAD / BM, 4), 512, SMEM_TOTAL>>>(
        xh, w1h, wc1h, partg, KB, 2, (KB / 2) / BK);

    finalize1<<<(MPAD * HID / 4) / 256, 256>>>(b1, bc1);

    // join 2: GEMM2 needs W2h; heads need W3t/Wc2t (prep overlapped GEMM1)
    cudaStreamWaitEvent(0, g_ss.evJoin2, 0);

    // GEMM2 split-K=8 (zpart always 0): 512 CTAs, 4 chunks each
    gemm_sk<<<dim3(HID / BN, MPAD / BM, 8), 512, SMEM_TOTAL>>>(
        h1h, w2h, w2h, partg, HID, 8, (HID / 8) / BK);

    finalize2<<<(NROI * HID / 4 + 255) / 256, 256>>>(b2);

    heads_kernel<<<NROI / HEADS_G, 256, 2 * HEADS_G * HID * (int)sizeof(float)>>>(b3, bc2, out);
}